// round 6
// baseline (speedup 1.0000x reference)
#include <cuda_runtime.h>
#include <cstdint>

#define NBOX 8192
#define M 64
#define D_IN 2376
#define H 1024
#define NCLS 150
#define IOU_T 0.01f
#define SEL_TARGET 2048

typedef unsigned int u32;
typedef unsigned short u16;
typedef unsigned char u8;

// -------- persistent device scratch (allocation-free rule) --------
__device__ int   g_sel[M];
__device__ float g_x[M * D_IN];
__device__ float g_h1[M * H];
__device__ float g_h2[M * H];
__device__ float g_part[1048576];     // split-K partials: [(sl*CB+cb)][64*32]
__device__ int   g_cnt[64];           // arrival counters per column tile

// ============================================================
// smem layout for sortnms kernel (bytes)
// ============================================================
#define RS_KEYA 0         // u32[8192]
#define RS_KEYB 32768     // u32[8192]
#define RS_IDXA 65536     // u16[8192]
#define RS_IDXB 81920     // u16[8192]
#define RS_GH   98304     // u32[32*256] (alias: sbin u32[4096]; NMS cbx/cord)
#define RS_RNK  131072    // u8[8192]
#define RS_TOT  139264    // u32[256]
#define RS_BASE 140288    // u32[256]
#define RS_WS   141312    // u32[32] warp sums
#define RS_SEL  141568    // int[64]
#define RS_SUPP 141824    // int[64]
#define RS_ST   142080    // int[8]
#define SORT_SMEM 142144

__device__ __forceinline__ bool iou_gt(float4 k, float ka, float4 c, float ca) {
    float ix1 = fmaxf(k.x, c.x), iy1 = fmaxf(k.y, c.y);
    float ix2 = fminf(k.z, c.z), iy2 = fminf(k.w, c.w);
    float iw = fmaxf(ix2 - ix1, 0.f), ih = fmaxf(iy2 - iy1, 0.f);
    float inter = iw * ih;
    return inter > IOU_T * (ka + ca - inter + 1e-9f);
}

// ============================================================
// Kernel 1: top-2048 select + 4x8bit radix + NMS + outputs + x-tail
// Single block, 1024 threads.
// ============================================================
__global__ void __launch_bounds__(1024) sortnms_kernel(
    const float* __restrict__ scores, const float* __restrict__ boxes,
    const int* __restrict__ labels, const float* __restrict__ embed_w,
    const float* __restrict__ bn_pos, const float* __restrict__ pos_w,
    const float* __restrict__ pos_b,
    float* __restrict__ d_out, int out_size)
{
    extern __shared__ unsigned char sm[];
    u32* keyA = (u32*)(sm + RS_KEYA);
    u32* keyB = (u32*)(sm + RS_KEYB);
    u16* idxA = (u16*)(sm + RS_IDXA);
    u16* idxB = (u16*)(sm + RS_IDXB);
    u32* gh   = (u32*)(sm + RS_GH);     // [group(32)][digit(256)]
    u8*  rnk  = (u8*) (sm + RS_RNK);
    u32* tot  = (u32*)(sm + RS_TOT);
    u32* base = (u32*)(sm + RS_BASE);
    u32* wsum = (u32*)(sm + RS_WS);
    int* s_sel  = (int*)(sm + RS_SEL);
    int* s_supp = (int*)(sm + RS_SUPP);
    int* st     = (int*)(sm + RS_ST);
    u32* sbin = gh;                      // alias (selection phase)
    float4* cbx = (float4*)(sm + RS_GH); // alias (NMS phase)
    int* cord   = (int*)(sm + RS_GH + 8192);

    const int tid = threadIdx.x;
    const int lane = tid & 31;
    const int wrp = tid >> 5;
    const unsigned FULL = 0xffffffffu;
    const float4* boxes4 = (const float4*)boxes;

    // ---- build keys (ascending key == descending score) + histogram ----
    for (int t = tid; t < 4096; t += 1024) sbin[t] = 0;
    __syncthreads();
    for (int t = tid; t < NBOX; t += 1024) {
        u32 b = __float_as_uint(scores[t]);
        u32 f = b ^ ((b >> 31) ? 0xFFFFFFFFu : 0x80000000u);
        u32 k = ~f;
        keyA[t] = k;
        atomicAdd(&sbin[k >> 20], 1u);
    }
    __syncthreads();

    // ---- exclusive scan of 4096 bins, find threshold bin B ----
    {
        int b0 = tid * 4;
        u32 v0 = sbin[b0], v1 = sbin[b0 + 1], v2 = sbin[b0 + 2], v3 = sbin[b0 + 3];
        u32 s = v0 + v1 + v2 + v3;
        u32 x = s;
        #pragma unroll
        for (int o = 1; o < 32; o <<= 1) {
            u32 y = __shfl_up_sync(FULL, x, o);
            if (lane >= o) x += y;
        }
        if (lane == 31) wsum[wrp] = x;
        u32 wex = x - s;
        __syncthreads();
        if (wrp == 0) {
            u32 v = wsum[lane];
            u32 xx = v;
            #pragma unroll
            for (int o = 1; o < 32; o <<= 1) {
                u32 y = __shfl_up_sync(FULL, xx, o);
                if (lane >= o) xx += y;
            }
            wsum[lane] = xx - v;
        }
        __syncthreads();
        u32 run = wsum[wrp] + wex;
        u32 vv[4] = { v0, v1, v2, v3 };
        #pragma unroll
        for (int i = 0; i < 4; ++i) {
            if (run < SEL_TARGET && run + vv[i] >= SEL_TARGET) {
                st[2] = b0 + i;               // threshold bin B
                st[3] = (int)(run + vv[i]);   // NSEL
            }
            run += vv[i];
        }
    }
    __syncthreads();
    const u32 B = (u32)st[2];
    const int NSEL = st[3];

    // ---- index-stable compaction of elements with bin <= B -> keyB/idxB ----
    {
        int t8 = tid * 8;
        u32 kv[8]; int pr[8]; u32 s = 0;
        #pragma unroll
        for (int i = 0; i < 8; ++i) {
            kv[i] = keyA[t8 + i];
            pr[i] = ((kv[i] >> 20) <= B) ? 1 : 0;
            s += pr[i];
        }
        u32 x = s;
        #pragma unroll
        for (int o = 1; o < 32; o <<= 1) {
            u32 y = __shfl_up_sync(FULL, x, o);
            if (lane >= o) x += y;
        }
        if (lane == 31) wsum[wrp] = x;
        u32 wex = x - s;
        __syncthreads();
        if (wrp == 0) {
            u32 v = wsum[lane];
            u32 xx = v;
            #pragma unroll
            for (int o = 1; o < 32; o <<= 1) {
                u32 y = __shfl_up_sync(FULL, xx, o);
                if (lane >= o) xx += y;
            }
            wsum[lane] = xx - v;
        }
        __syncthreads();
        u32 pos = wsum[wrp] + wex;
        #pragma unroll
        for (int i = 0; i < 8; ++i) {
            if (pr[i]) { keyB[pos] = kv[i]; idxB[pos] = (u16)(t8 + i); pos++; }
        }
    }
    __syncthreads();

    // ---- 4-pass 8-bit stable LSD radix on NSEL elements (src keyB) ----
    u32 *src = keyB, *dst = keyA;
    u16 *isrc = idxB, *idst = idxA;
    for (int p = 0; p < 4; ++p) {
        const int sh = p * 8;
        for (int t = tid; t < 8192; t += 1024) gh[t] = 0;
        __syncthreads();

        // phase A: per-warp-chunk (256 elems) histogram + ranks
        #pragma unroll
        for (int b = 0; b < 8; ++b) {
            int e = wrp * 256 + b * 32 + lane;
            bool valid = (e < NSEL);
            u32 k = valid ? src[e] : 0u;
            u32 d = (k >> sh) & 255u;
            u32 mkey = valid ? d : (256u + lane);
            unsigned m = __match_any_sync(FULL, mkey);
            unsigned lt = m & ((1u << lane) - 1u);
            u32 cnt = gh[wrp * 256 + d];
            __syncwarp();
            if (valid) {
                rnk[e] = (u8)(cnt + __popc(lt));
                if (lt == 0) gh[wrp * 256 + d] = cnt + __popc(m);
            }
            __syncwarp();
        }
        __syncthreads();

        // phase B: per-digit scan over 32 groups (each warp owns 8 digits)
        #pragma unroll
        for (int i = 0; i < 8; ++i) {
            int d = wrp * 8 + i;
            u32 v = gh[lane * 256 + d];
            u32 x = v;
            #pragma unroll
            for (int o = 1; o < 32; o <<= 1) {
                u32 y = __shfl_up_sync(FULL, x, o);
                if (lane >= o) x += y;
            }
            gh[lane * 256 + d] = x - v;
            if (lane == 31) tot[d] = x;
        }
        __syncthreads();
        // digit base scan (warp 0)
        if (wrp == 0) {
            u32 carry = 0;
            #pragma unroll
            for (int i = 0; i < 8; ++i) {
                int d = i * 32 + lane;
                u32 v = tot[d];
                u32 x = v;
                #pragma unroll
                for (int o = 1; o < 32; o <<= 1) {
                    u32 y = __shfl_up_sync(FULL, x, o);
                    if (lane >= o) x += y;
                }
                base[d] = x - v + carry;
                carry += __shfl_sync(FULL, x, 31);
            }
        }
        __syncthreads();

        // phase C: stable scatter
        #pragma unroll
        for (int b = 0; b < 8; ++b) {
            int e = wrp * 256 + b * 32 + lane;
            if (e < NSEL) {
                u32 k = src[e];
                u32 d = (k >> sh) & 255u;
                u32 pos = base[d] + gh[wrp * 256 + d] + rnk[e];
                dst[pos] = k;
                idst[pos] = isrc[e];
            }
        }
        __syncthreads();
        u32* tk = src; src = dst; dst = tk;
        u16* ti = isrc; isrc = idst; idst = ti;
    }
    // after 4 passes result back in keyB/idxB (src == keyB)

    // ---- greedy NMS over sorted candidates, chunks of 512 ----
    float4 kb0 = make_float4(0, 0, 0, 0), kb1 = make_float4(0, 0, 0, 0);
    float ka0 = 0.f, ka1 = 0.f;
    int kept = 0, supp = 0;
    if (tid == 0) { st[0] = 0; st[1] = 0; }
    __syncthreads();

    for (int c0 = 0; c0 < NSEL; c0 += 512) {
        const int cnt = min(512, NSEL - c0);
        if (tid < cnt) {
            int oi = (int)isrc[c0 + tid];
            cord[tid] = oi;
            cbx[tid] = boxes4[oi];
        }
        __syncthreads();

        if (tid < 32) {
            #pragma unroll 1
            for (int ii = 0; ii < cnt; ++ii) {
                float4 c = cbx[ii];
                float ca = (c.z - c.x) * (c.w - c.y);
                bool sup = false;
                if (tid < kept)      sup  = iou_gt(kb0, ka0, c, ca);
                if (tid + 32 < kept) sup |= iou_gt(kb1, ka1, c, ca);
                unsigned m = __ballot_sync(FULL, sup);
                if (m == 0) {
                    int slot = kept;
                    if (slot < 32) { if (tid == slot)      { kb0 = c; ka0 = ca; } }
                    else           { if (tid == slot - 32) { kb1 = c; ka1 = ca; } }
                    if (tid == 0) s_sel[slot] = cord[ii];
                    kept++;
                    if (kept == 64) break;
                } else if (supp < 64) {
                    if (tid == 0) s_supp[supp] = cord[ii];
                    supp++;
                }
            }
            if (tid == 0) { st[0] = kept; st[1] = supp; }
        }
        __syncthreads();
        if (st[0] >= 64) break;
        __syncthreads();
    }

    // ---- final selection + labels/scores outputs ----
    const int keptF = st[0];
    if (tid < 64) {
        int oi = (tid < keptF) ? s_sel[tid] : s_supp[tid - keptF];
        g_sel[tid] = oi;
        if (9600 + tid < out_size) d_out[9600 + tid] = (float)labels[oi];
        if (9664 + tid < out_size) d_out[9664 + tid] = scores[oi];
    }
    __syncthreads();

    // ---- x tail: embed (cols 2048..2247) + pos (cols 2248..2375) ----
    for (int t = tid; t < 64 * 200; t += 1024) {
        int r = t / 200, c = t - r * 200;
        int lab = labels[g_sel[r]] - 1;
        g_x[r * D_IN + 2048 + c] = embed_w[lab * 200 + c];
    }
    for (int t = tid; t < 64 * 128; t += 1024) {
        int r = t >> 7, c = t & 127;
        int oi = g_sel[r];
        float x1 = boxes[oi * 4 + 0], y1 = boxes[oi * 4 + 1];
        float x2 = boxes[oi * 4 + 2], y2 = boxes[oi * 4 + 3];
        float w = x2 - x1 + 1.f, h = y2 - y1 + 1.f;
        float cs[4] = { x1 + 0.5f * w, y1 + 0.5f * h, w, h };
        float acc = pos_b[c];
        #pragma unroll
        for (int i = 0; i < 4; ++i) {
            float v = (cs[i] - bn_pos[8 + i]) * rsqrtf(bn_pos[12 + i] + 1e-5f)
                      * bn_pos[i] + bn_pos[4 + i];
            acc += v * pos_w[i * 128 + c];
        }
        g_x[r * D_IN + 2248 + c] = fmaxf(acc, 0.f);
    }
}

// ============================================================
// Kernel 2: gather features rows into g_x (cols 0..2047)
// ============================================================
__global__ void __launch_bounds__(256) gatherfeat_kernel(
    const float* __restrict__ features)
{
    const int b = blockIdx.x, tid = threadIdx.x;
    const int oi = g_sel[b];
    const float4* src = (const float4*)(features + (size_t)oi * 2048);
    float4* dst = (float4*)(g_x + b * D_IN);
    #pragma unroll
    for (int i = tid; i < 512; i += 256) dst[i] = src[i];
}

// ============================================================
// cp.async helpers
// ============================================================
__device__ __forceinline__ unsigned smem_u32p(const void* p) {
    return (unsigned)__cvta_generic_to_shared(p);
}
__device__ __forceinline__ void cp16(unsigned dst, const float* src) {
    asm volatile("cp.async.cg.shared.global [%0], [%1], 16;" :: "r"(dst), "l"(src));
}
__device__ __forceinline__ void cp4(unsigned dst, const float* src) {
    asm volatile("cp.async.ca.shared.global [%0], [%1], 4;" :: "r"(dst), "l"(src));
}
#define CP_COMMIT() asm volatile("cp.async.commit_group;" ::: "memory")
#define CP_WAIT2()  asm volatile("cp.async.wait_group 2;" ::: "memory")

// ============================================================
// Kernel 3: split-K GEMM, 64x32 tiles, 256 threads, 4x2 thread tile.
// W: 4-stage cp.async pipeline (DRAM stream). A: LDG.128 + STS transpose,
// double-buffered (A is L2-resident). Fused last-block reduce epilogue.
// K-slice lengths must be multiples of 8; chunks of 16 (tail mult of 4).
// ============================================================
template<int ASEL, int FULLN, int S>
__global__ void __launch_bounds__(256) gemm4_kernel(
    const float* __restrict__ Wm, const float* __restrict__ bias,
    const float* __restrict__ bn, float* __restrict__ dest,
    int N, int K, int kps, int CB, int outsel, int bnrelu)
{
    __shared__ float As[2][16][68];   // [buf][kk][row] transposed, pad 68
    __shared__ float Ws[4][16][36];   // [stage][kk][col], pad 36
    __shared__ int s_last;

    const int tid = threadIdx.x;
    const int cb = blockIdx.x, sl = blockIdx.y;
    const int trow = (tid >> 4) * 4;   // 0..60
    const int tcol = (tid & 15) * 2;   // 0..30
    const int k0 = sl * kps;
    const int k1 = min(k0 + kps, K);

    const float* __restrict__ A = (ASEL == 0) ? g_x : ((ASEL == 1) ? g_h1 : g_h2);
    const int lda = (ASEL == 0) ? D_IN : H;

    // A-staging mapping: thread -> (row, kk-quad)
    const int ar = tid >> 2;          // 0..63
    const int ak4 = (tid & 3) * 4;    // 0,4,8,12

    if (!FULLN) {
        for (int t = tid; t < 4 * 16 * 36; t += 256) ((float*)Ws)[t] = 0.f;
    }
    __syncthreads();

    float acc[4][2] = {};

    auto stageW = [&](int buf, int kb) {
        if (FULLN) {
            if (tid < 128) {
                int kk = tid >> 3, n4 = (tid & 7) * 4;
                int j = kb + kk;
                if (j < k1)
                    cp16(smem_u32p(&Ws[buf][kk][n4]), Wm + (size_t)j * N + cb * 32 + n4);
            }
        } else {
            #pragma unroll
            for (int i = 0; i < 2; ++i) {
                int idx = tid + 256 * i;
                int kk = idx >> 5, c = idx & 31;
                int j = kb + kk, col = cb * 32 + c;
                if (j < k1 && col < N)
                    cp4(smem_u32p(&Ws[buf][kk][c]), Wm + (size_t)j * N + col);
            }
        }
    };
    auto ldgA = [&](int kb, float4& v) {
        int j = kb + ak4;
        if (j < k1) v = *reinterpret_cast<const float4*>(A + (size_t)ar * lda + j);
    };
    auto stsA = [&](int buf, int kb, const float4& v) {
        int j = kb + ak4;
        if (j < k1) {
            As[buf][ak4 + 0][ar] = v.x;
            As[buf][ak4 + 1][ar] = v.y;
            As[buf][ak4 + 2][ar] = v.z;
            As[buf][ak4 + 3][ar] = v.w;
        }
    };

    const int nChunk = (k1 - k0 + 15) >> 4;

    // prologue: W stages 0..2; A chunk 0
    #pragma unroll
    for (int s = 0; s < 3; ++s) {
        if (s < nChunk) stageW(s, k0 + s * 16);
        CP_COMMIT();
    }
    {
        float4 a0 = make_float4(0, 0, 0, 0);
        ldgA(k0, a0);
        stsA(0, k0, a0);
    }

    for (int c = 0; c < nChunk; ++c) {
        CP_WAIT2();
        __syncthreads();

        // prefetch A for c+1 into registers (blocking load overlapped by compute)
        float4 anext = make_float4(0, 0, 0, 0);
        if (c + 1 < nChunk) ldgA(k0 + (c + 1) * 16, anext);

        // issue W stage c+3
        if (c + 3 < nChunk) stageW((c + 3) & 3, k0 + (c + 3) * 16);
        CP_COMMIT();

        const int kbn = min(16, k1 - (k0 + c * 16));
        const float (*Ab)[68] = As[c & 1];
        const float (*Wb)[36] = Ws[c & 3];

        #define KK_BODY(kk)                                                     \
        {                                                                       \
            float4 a = *reinterpret_cast<const float4*>(&Ab[kk][trow]);         \
            float2 w = *reinterpret_cast<const float2*>(&Wb[kk][tcol]);         \
            acc[0][0] += a.x * w.x; acc[0][1] += a.x * w.y;                     \
            acc[1][0] += a.y * w.x; acc[1][1] += a.y * w.y;                     \
            acc[2][0] += a.z * w.x; acc[2][1] += a.z * w.y;                     \
            acc[3][0] += a.w * w.x; acc[3][1] += a.w * w.y;                     \
        }
        if (kbn == 16) {
            #pragma unroll
            for (int kk = 0; kk < 16; ++kk) KK_BODY(kk)
        } else {
            #pragma unroll 4
            for (int kk = 0; kk < kbn; ++kk) KK_BODY(kk)
        }
        #undef KK_BODY

        if (c + 1 < nChunk) stsA((c + 1) & 1, k0 + (c + 1) * 16, anext);
    }

    // ---- write 64x32 partial tile ----
    float* p = g_part + (size_t)(sl * CB + cb) * 2048;
    #pragma unroll
    for (int r = 0; r < 4; ++r)
        *reinterpret_cast<float2*>(&p[(trow + r) * 32 + tcol]) =
            make_float2(acc[r][0], acc[r][1]);

    // ---- last block per column tile reduces + epilogue ----
    __syncthreads();
    if (tid == 0) {
        __threadfence();
        int old = atomicAdd(&g_cnt[cb], 1);
        s_last = (old == S - 1) ? 1 : 0;
    }
    __syncthreads();
    if (!s_last) return;
    __threadfence();

    float* out = (outsel == 1) ? g_h1 : ((outsel == 2) ? g_h2 : dest);
    const int ldo = (outsel == 3) ? N : H;
    for (int idx = tid; idx < 2048; idx += 256) {
        int r = idx >> 5, cc = idx & 31;
        int col = cb * 32 + cc;
        if (FULLN || col < N) {
            float s = 0.f;
            #pragma unroll
            for (int si = 0; si < S; ++si)
                s += g_part[(size_t)(si * CB + cb) * 2048 + idx];
            s += bias[col];
            if (bnrelu) {
                s = (s - bn[2 * N + col]) * rsqrtf(bn[3 * N + col] + 1e-5f)
                    * bn[col] + bn[N + col];
                s = fmaxf(s, 0.f);
            }
            out[r * ldo + col] = s;
        }
    }
    if (tid == 0) g_cnt[cb] = 0;
}

// ============================================================
extern "C" void kernel_launch(void* const* d_in, const int* in_sizes, int n_in,
                              void* d_out_v, int out_size)
{
    const float* boxes    = (const float*)d_in[0];
    const float* scores   = (const float*)d_in[1];
    const int*   labels   = (const int*)  d_in[2];
    const float* features = (const float*)d_in[3];
    const float* embed_w  = (const float*)d_in[4];
    const float* bn_pos   = (const float*)d_in[5];
    const float* pos_w    = (const float*)d_in[6];
    const float* pos_b    = (const float*)d_in[7];
    const float* lin1_w   = (const float*)d_in[8];
    const float* lin1_b   = (const float*)d_in[9];
    const float* bn1      = (const float*)d_in[10];
    const float* lin2_w   = (const float*)d_in[11];
    const float* lin2_b   = (const float*)d_in[12];
    const float* bn2      = (const float*)d_in[13];
    const float* lin3_w   = (const float*)d_in[14];
    const float* lin3_b   = (const float*)d_in[15];
    const float* bn3      = (const float*)d_in[16];
    const float* lin4_w   = (const float*)d_in[17];
    const float* lin4_b   = (const float*)d_in[18];
    float* d_out = (float*)d_out_v;

    cudaFuncSetAttribute(sortnms_kernel,
                         cudaFuncAttributeMaxDynamicSharedMemorySize, SORT_SMEM);

    sortnms_kernel<<<1, 1024, SORT_SMEM>>>(scores, boxes, labels, embed_w,
                                           bn_pos, pos_w, pos_b, d_out, out_size);
    gatherfeat_kernel<<<64, 256>>>(features);

    // L1: [64,2376]@[2376,1024]  CB=32, S=16, kps=152 (15x152 + 96, mult 8)
    gemm4_kernel<0, 1, 16><<<dim3(32, 16), 256>>>(
        lin1_w, lin1_b, bn1, d_out, H, D_IN, 152, 32, 1, 1);

    // L2: [64,1024]@[1024,1024]  CB=32, S=16, kps=64
    gemm4_kernel<1, 1, 16><<<dim3(32, 16), 256>>>(
        lin2_w, lin2_b, bn2, d_out, H, H, 64, 32, 2, 1);

    // L3: reads g_h2, writes g_h1
    gemm4_kernel<2, 1, 16><<<dim3(32, 16), 256>>>(
        lin3_w, lin3_b, bn3, d_out, H, H, 64, 32, 1, 1);

    // L4: [64,1024]@[1024,150]  CB=5, S=16, kps=64, no BN/ReLU, to d_out
    gemm4_kernel<1, 0, 16><<<dim3(5, 16), 256>>>(
        lin4_w, lin4_b, bn1, d_out, NCLS, H, 64, 5, 3, 0);
}

// round 9
// speedup vs baseline: 1.8654x; 1.8654x over previous
#include <cuda_runtime.h>
#include <cstdint>

#define NBOX 8192
#define M 64
#define D_IN 2376
#define H 1024
#define NCLS 150
#define IOU_T 0.01f
#define G 256

typedef unsigned int u32;
typedef unsigned long long u64;
typedef unsigned short u16;

// -------- persistent device scratch (allocation-free rule) --------
__device__ int   g_sel[M];
__device__ float g_x[M * D_IN];
__device__ float g_h1[M * H];
__device__ float g_h2[M * H];
__device__ float g_part[1048576];   // [slot(sl*CB+cb)][64*64]
__device__ int   g_bar;
__device__ int   g_exit;

__device__ __forceinline__ bool iou_gt(float4 k, float ka, float4 c, float ca) {
    float ix1 = fmaxf(k.x, c.x), iy1 = fmaxf(k.y, c.y);
    float ix2 = fminf(k.z, c.z), iy2 = fminf(k.w, c.w);
    float iw = fmaxf(ix2 - ix1, 0.f), ih = fmaxf(iy2 - iy1, 0.f);
    float inter = iw * ih;
    return inter > IOU_T * (ka + ca - inter + 1e-9f);
}

// ============================================================
// Kernel 1: top-512 select + bitonic sort + NMS + outputs + x-tail
// Single block, 1024 threads, static smem (~44KB).
// ============================================================
__global__ void __launch_bounds__(1024) sortnms_kernel(
    const float* __restrict__ scores, const float* __restrict__ boxes,
    const int* __restrict__ labels, const float* __restrict__ embed_w,
    const float* __restrict__ bn_pos, const float* __restrict__ pos_w,
    const float* __restrict__ pos_b,
    float* __restrict__ d_out, int out_size)
{
    __shared__ u32 bins[4096];
    __shared__ u64 skey[2048];
    __shared__ float4 cbx[512];
    __shared__ int cord[512];
    __shared__ u32 wsum[32];
    __shared__ int s_sel[64], s_supp[64], st[8];
    __shared__ int s_cnt;

    const int tid = threadIdx.x, lane = tid & 31, wrp = tid >> 5;
    const unsigned FULL = 0xffffffffu;
    const float4* boxes4 = (const float4*)boxes;

    // ---- histogram of top-12 key bits ----
    for (int t = tid; t < 4096; t += 1024) bins[t] = 0;
    if (tid == 0) s_cnt = 0;
    __syncthreads();
    for (int t = tid; t < NBOX; t += 1024) {
        u32 b = __float_as_uint(scores[t]);
        u32 f = b ^ ((b >> 31) ? 0xFFFFFFFFu : 0x80000000u);
        atomicAdd(&bins[(~f) >> 20], 1u);
    }
    __syncthreads();

    // ---- scan 4096 bins, threshold bin for >=512 selected ----
    {
        int b0 = tid * 4;
        u32 v0 = bins[b0], v1 = bins[b0 + 1], v2 = bins[b0 + 2], v3 = bins[b0 + 3];
        u32 s = v0 + v1 + v2 + v3, x = s;
        #pragma unroll
        for (int o = 1; o < 32; o <<= 1) {
            u32 y = __shfl_up_sync(FULL, x, o);
            if (lane >= o) x += y;
        }
        if (lane == 31) wsum[wrp] = x;
        u32 wex = x - s;
        __syncthreads();
        if (wrp == 0) {
            u32 v = wsum[lane], xx = v;
            #pragma unroll
            for (int o = 1; o < 32; o <<= 1) {
                u32 y = __shfl_up_sync(FULL, xx, o);
                if (lane >= o) xx += y;
            }
            wsum[lane] = xx - v;
        }
        __syncthreads();
        u32 run = wsum[wrp] + wex;
        u32 vv[4] = { v0, v1, v2, v3 };
        #pragma unroll
        for (int i = 0; i < 4; ++i) {
            if (run < 512 && run + vv[i] >= 512) {
                st[2] = b0 + i;
                st[3] = (int)(run + vv[i]);
                st[4] = (int)run;
            }
            run += vv[i];
        }
    }
    __syncthreads();
    u32 B; int NSEL;
    if (st[3] <= 2048) { B = (u32)st[2]; NSEL = st[3]; }
    else               { B = (u32)st[2] - 1; NSEL = st[4]; }   // tie-bin overflow fallback

    // ---- unordered compaction (sort canonicalizes) ----
    for (int t = tid; t < NBOX; t += 1024) {
        u32 b = __float_as_uint(scores[t]);
        u32 f = b ^ ((b >> 31) ? 0xFFFFFFFFu : 0x80000000u);
        u32 k = ~f;
        if ((k >> 20) <= B) {
            int pos = atomicAdd(&s_cnt, 1);
            if (pos < 2048) skey[pos] = ((u64)k << 32) | (u32)t;
        }
    }
    __syncthreads();
    for (int t = NSEL + tid; t < 2048; t += 1024) skey[t] = ~0ull;
    __syncthreads();

    // ---- bitonic sort 2048 u64 ascending ----
    for (int size = 2; size <= 2048; size <<= 1) {
        for (int stride = size >> 1; stride > 0; stride >>= 1) {
            __syncthreads();
            int i = ((tid & ~(stride - 1)) << 1) | (tid & (stride - 1));
            int j = i | stride;
            bool up = ((i & size) == 0);
            u64 a = skey[i], b2 = skey[j];
            if ((a > b2) == up) { skey[i] = b2; skey[j] = a; }
        }
    }
    __syncthreads();

    // ---- greedy NMS over sorted candidates, chunks of 512 ----
    float4 kb0 = make_float4(0, 0, 0, 0), kb1 = make_float4(0, 0, 0, 0);
    float ka0 = 0.f, ka1 = 0.f;
    int kept = 0, supp = 0;
    if (tid == 0) { st[0] = 0; st[1] = 0; }
    __syncthreads();

    for (int c0 = 0; c0 < NSEL; c0 += 512) {
        const int cnt = min(512, NSEL - c0);
        if (tid < cnt) {
            int oi = (int)(u32)(skey[c0 + tid] & 0xffffffffu);
            cord[tid] = oi;
            cbx[tid] = boxes4[oi];
        }
        __syncthreads();

        if (tid < 32) {
            #pragma unroll 1
            for (int ii = 0; ii < cnt; ++ii) {
                float4 c = cbx[ii];
                float ca = (c.z - c.x) * (c.w - c.y);
                bool sup = false;
                if (tid < kept)      sup  = iou_gt(kb0, ka0, c, ca);
                if (tid + 32 < kept) sup |= iou_gt(kb1, ka1, c, ca);
                unsigned m = __ballot_sync(FULL, sup);
                if (m == 0) {
                    int slot = kept;
                    if (slot < 32) { if (tid == slot)      { kb0 = c; ka0 = ca; } }
                    else           { if (tid == slot - 32) { kb1 = c; ka1 = ca; } }
                    if (tid == 0) s_sel[slot] = cord[ii];
                    kept++;
                    if (kept == 64) break;
                } else if (supp < 64) {
                    if (tid == 0) s_supp[supp] = cord[ii];
                    supp++;
                }
            }
            if (tid == 0) { st[0] = kept; st[1] = supp; }
        }
        __syncthreads();
        if (st[0] >= 64) break;
        __syncthreads();
    }

    // ---- selection + labels/scores outputs ----
    const int keptF = st[0];
    if (tid < 64) {
        int oi = (tid < keptF) ? s_sel[tid] : s_supp[tid - keptF];
        g_sel[tid] = oi;
        if (9600 + tid < out_size) d_out[9600 + tid] = (float)labels[oi];
        if (9664 + tid < out_size) d_out[9664 + tid] = scores[oi];
    }
    __syncthreads();

    // ---- x tail: embed (2048..2247) + pos (2248..2375) ----
    for (int t = tid; t < 64 * 200; t += 1024) {
        int r = t / 200, c = t - r * 200;
        int lab = labels[g_sel[r]] - 1;
        g_x[r * D_IN + 2048 + c] = embed_w[lab * 200 + c];
    }
    for (int t = tid; t < 64 * 128; t += 1024) {
        int r = t >> 7, c = t & 127;
        int oi = g_sel[r];
        float x1 = boxes[oi * 4 + 0], y1 = boxes[oi * 4 + 1];
        float x2 = boxes[oi * 4 + 2], y2 = boxes[oi * 4 + 3];
        float w = x2 - x1 + 1.f, h = y2 - y1 + 1.f;
        float cs[4] = { x1 + 0.5f * w, y1 + 0.5f * h, w, h };
        float acc = pos_b[c];
        #pragma unroll
        for (int i = 0; i < 4; ++i) {
            float v = (cs[i] - bn_pos[8 + i]) * rsqrtf(bn_pos[12 + i] + 1e-5f)
                      * bn_pos[i] + bn_pos[4 + i];
            acc += v * pos_w[i * 128 + c];
        }
        g_x[r * D_IN + 2248 + c] = fmaxf(acc, 0.f);
    }
}

// ============================================================
// cp.async helpers
//  cp16: .cg (L2-only) — used for all buffers that are written and
//        re-read within the persistent kernel (g_x/g_h1/g_h2) + weights.
//  cp4:  .ca (L1 ok)  — ONLY used on lin4_w, a read-only input.
// ============================================================
__device__ __forceinline__ unsigned smem_u32p(const void* p) {
    return (unsigned)__cvta_generic_to_shared(p);
}
__device__ __forceinline__ void cp16(unsigned dst, const float* src) {
    asm volatile("cp.async.cg.shared.global [%0], [%1], 16;" :: "r"(dst), "l"(src));
}
__device__ __forceinline__ void cp4(unsigned dst, const float* src) {
    asm volatile("cp.async.ca.shared.global [%0], [%1], 4;" :: "r"(dst), "l"(src));
}
#define CP_COMMIT() asm volatile("cp.async.commit_group;" ::: "memory")
#define CP_WAIT2()  asm volatile("cp.async.wait_group 2;" ::: "memory")
#define CP_WAIT0()  asm volatile("cp.async.wait_group 0;" ::: "memory")

// ============================================================
// Persistent-kernel global barrier.
// ALL threads release-fence before arrival (grid.sync pattern),
// so every block's global stores are visible after the barrier.
// ============================================================
__device__ __forceinline__ void gsync(int target, int tid) {
    __threadfence();               // release: order this thread's stores
    __syncthreads();
    if (tid == 0) {
        atomicAdd(&g_bar, 1);
        while (*(volatile int*)&g_bar < target) __nanosleep(64);
    }
    __syncthreads();
    __threadfence();               // acquire side
}

// ============================================================
// GEMM phase: 64x64 col-tile x K-slice, 4-stage cp.async pipeline
// (A and W both via smem). K-slice lengths must be multiples of 8.
// ============================================================
template<int FULLN>
__device__ void gemm_phase(const float* __restrict__ A, int lda,
                           const float* __restrict__ Wm, int N,
                           int cb, int sl, int kps, int K, int CB, int tid,
                           float (&As)[4][64][20], float (&Ws)[4][16][68])
{
    const int row0 = (tid >> 4) * 4;
    const int cl   = (tid & 15) * 4;
    const int k0 = sl * kps;
    const int k1 = min(k0 + kps, K);

    if (!FULLN) {
        for (int t = tid; t < 4 * 16 * 68; t += 256) (&Ws[0][0][0])[t] = 0.f;
        __syncthreads();
    }

    float acc[4][4] = {};

    auto stageA = [&](int buf, int kb) {
        const int r = tid >> 2;
        const int kk4 = (tid & 3) * 4;
        const int j = kb + kk4;
        if (j < k1)
            cp16(smem_u32p(&As[buf][r][kk4]), A + (size_t)r * lda + j);
    };
    auto stageW = [&](int buf, int kb) {
        if (FULLN) {
            const int kk = tid >> 4;
            const int n4 = (tid & 15) * 4;
            const int j = kb + kk;
            if (j < k1)
                cp16(smem_u32p(&Ws[buf][kk][n4]), Wm + (size_t)j * N + cb * 64 + n4);
        } else {
            #pragma unroll
            for (int i = 0; i < 4; ++i) {
                int idx = tid + 256 * i;           // 16 kk x 64 cols
                int kk = idx >> 6, c = idx & 63;
                int j = kb + kk, col = cb * 64 + c;
                if (j < k1 && col < N)
                    cp4(smem_u32p(&Ws[buf][kk][c]), Wm + (size_t)j * N + col);
            }
        }
    };

    const int nChunk = (k1 - k0 + 15) >> 4;
    #pragma unroll
    for (int s = 0; s < 3; ++s) {
        if (s < nChunk) { stageA(s, k0 + s * 16); stageW(s, k0 + s * 16); }
        CP_COMMIT();
    }

    for (int c = 0; c < nChunk; ++c) {
        CP_WAIT2();
        __syncthreads();
        {
            const int s = c + 3;
            if (s < nChunk) { stageA(s & 3, k0 + s * 16); stageW(s & 3, k0 + s * 16); }
            CP_COMMIT();
        }
        const int kbn = min(16, k1 - (k0 + c * 16));
        const float (*Ab)[20] = As[c & 3];
        const float (*Wb)[68] = Ws[c & 3];

        #define KK_BODY(kk)                                                    \
        {                                                                      \
            float a0 = Ab[row0 + 0][kk], a1 = Ab[row0 + 1][kk];                \
            float a2 = Ab[row0 + 2][kk], a3 = Ab[row0 + 3][kk];                \
            float4 w = *reinterpret_cast<const float4*>(&Wb[kk][cl]);          \
            acc[0][0] += a0 * w.x; acc[0][1] += a0 * w.y;                      \
            acc[0][2] += a0 * w.z; acc[0][3] += a0 * w.w;                      \
            acc[1][0] += a1 * w.x; acc[1][1] += a1 * w.y;                      \
            acc[1][2] += a1 * w.z; acc[1][3] += a1 * w.w;                      \
            acc[2][0] += a2 * w.x; acc[2][1] += a2 * w.y;                      \
            acc[2][2] += a2 * w.z; acc[2][3] += a2 * w.w;                      \
            acc[3][0] += a3 * w.x; acc[3][1] += a3 * w.y;                      \
            acc[3][2] += a3 * w.z; acc[3][3] += a3 * w.w;                      \
        }
        if (kbn == 16) {
            #pragma unroll
            for (int kk = 0; kk < 16; ++kk) KK_BODY(kk)
        } else {
            #pragma unroll 8
            for (int kk = 0; kk < kbn; ++kk) KK_BODY(kk)
        }
        #undef KK_BODY
    }

    CP_WAIT0();          // drain before smem reuse in next phase
    __syncthreads();

    float* p = g_part + (size_t)(sl * CB + cb) * 4096;
    #pragma unroll
    for (int r = 0; r < 4; ++r)
        *reinterpret_cast<float4*>(&p[(row0 + r) * 64 + cl]) =
            make_float4(acc[r][0], acc[r][1], acc[r][2], acc[r][3]);
}

// 1024-col layer reduce: 65536 elems over 256 blocks x 256 threads (1 each)
__device__ __forceinline__ void reduce_h(
    const float* __restrict__ bias, const float* __restrict__ bn,
    float* __restrict__ out, int vb, int tid)
{
    int idx = vb * 256 + tid;
    int r = idx >> 10, col = idx & 1023;
    int cb = col >> 6, c = col & 63;
    float s = 0.f;
    #pragma unroll
    for (int si = 0; si < 16; ++si)
        s += __ldcg(&g_part[(size_t)(si * 16 + cb) * 4096 + r * 64 + c]);
    s += bias[col];
    s = (s - bn[2048 + col]) * rsqrtf(bn[3072 + col] + 1e-5f) * bn[col] + bn[1024 + col];
    out[r * 1024 + col] = fmaxf(s, 0.f);
}

// ============================================================
// Kernel 2: persistent fused MLP (gather + 4 layers), grid=256.
// __launch_bounds__(256,2) caps regs so 2 blocks/SM fit ->
// all 256 blocks co-resident on 148 SMs (no barrier deadlock).
// ============================================================
__global__ void __launch_bounds__(256, 2) mlp_kernel(
    const float* __restrict__ features,
    const float* __restrict__ lin1_w, const float* __restrict__ lin1_b,
    const float* __restrict__ bn1,
    const float* __restrict__ lin2_w, const float* __restrict__ lin2_b,
    const float* __restrict__ bn2,
    const float* __restrict__ lin3_w, const float* __restrict__ lin3_b,
    const float* __restrict__ bn3,
    const float* __restrict__ lin4_w, const float* __restrict__ lin4_b,
    float* __restrict__ d_out)
{
    __shared__ float As[4][64][20];
    __shared__ float Ws[4][16][68];
    const int tid = threadIdx.x;
    const int vb = blockIdx.x;
    int tgt = G;

    // phase 0: gather features rows into g_x cols [0,2048)
    if (tid < 128) {
        int fi = vb * 128 + tid;              // 32768 float4 total
        int r = fi >> 9, c = fi & 511;
        int oi = g_sel[r];
        float4 v = ((const float4*)(features + (size_t)oi * 2048))[c];
        ((float4*)(g_x + r * D_IN))[c] = v;
    }
    gsync(tgt, tid); tgt += G;

    // L1: [64,2376]@[2376,1024], 16 cb x 16 sl, kps=152 (15x152+96)
    gemm_phase<1>(g_x, D_IN, lin1_w, H, vb & 15, vb >> 4, 152, D_IN, 16, tid, As, Ws);
    gsync(tgt, tid); tgt += G;
    reduce_h(lin1_b, bn1, g_h1, vb, tid);
    gsync(tgt, tid); tgt += G;

    // L2
    gemm_phase<1>(g_h1, H, lin2_w, H, vb & 15, vb >> 4, 64, H, 16, tid, As, Ws);
    gsync(tgt, tid); tgt += G;
    reduce_h(lin2_b, bn2, g_h2, vb, tid);
    gsync(tgt, tid); tgt += G;

    // L3
    gemm_phase<1>(g_h2, H, lin3_w, H, vb & 15, vb >> 4, 64, H, 16, tid, As, Ws);
    gsync(tgt, tid); tgt += G;
    reduce_h(lin3_b, bn3, g_h1, vb, tid);
    gsync(tgt, tid); tgt += G;

    // L4: [64,1024]@[1024,150], 3 cb x 16 sl (48 blocks), kps=64
    if (vb < 48)
        gemm_phase<0>(g_h1, H, lin4_w, NCLS, vb % 3, vb / 3, 64, H, 3, tid, As, Ws);
    gsync(tgt, tid); tgt += G;

    // L4 reduce: 9600 elems
    {
        int idx = vb * 256 + tid;
        if (idx < 9600) {
            int r = idx / 150, col = idx - r * 150;
            int cb = col >> 6, c = col & 63;
            float s = 0.f;
            #pragma unroll
            for (int si = 0; si < 16; ++si)
                s += __ldcg(&g_part[(size_t)(si * 3 + cb) * 4096 + r * 64 + c]);
            d_out[idx] = s + lin4_b[col];
        }
    }

    // exit: last block resets barrier counters for graph replay
    __syncthreads();
    if (tid == 0) {
        __threadfence();
        int old = atomicAdd(&g_exit, 1);
        if (old == G - 1) {
            g_bar = 0;
            g_exit = 0;
            __threadfence();
        }
    }
}

// ============================================================
extern "C" void kernel_launch(void* const* d_in, const int* in_sizes, int n_in,
                              void* d_out_v, int out_size)
{
    const float* boxes    = (const float*)d_in[0];
    const float* scores   = (const float*)d_in[1];
    const int*   labels   = (const int*)  d_in[2];
    const float* features = (const float*)d_in[3];
    const float* embed_w  = (const float*)d_in[4];
    const float* bn_pos   = (const float*)d_in[5];
    const float* pos_w    = (const float*)d_in[6];
    const float* pos_b    = (const float*)d_in[7];
    const float* lin1_w   = (const float*)d_in[8];
    const float* lin1_b   = (const float*)d_in[9];
    const float* bn1      = (const float*)d_in[10];
    const float* lin2_w   = (const float*)d_in[11];
    const float* lin2_b   = (const float*)d_in[12];
    const float* bn2      = (const float*)d_in[13];
    const float* lin3_w   = (const float*)d_in[14];
    const float* lin3_b   = (const float*)d_in[15];
    const float* bn3      = (const float*)d_in[16];
    const float* lin4_w   = (const float*)d_in[17];
    const float* lin4_b   = (const float*)d_in[18];
    float* d_out = (float*)d_out_v;

    sortnms_kernel<<<1, 1024>>>(scores, boxes, labels, embed_w,
                                bn_pos, pos_w, pos_b, d_out, out_size);

    mlp_kernel<<<G, 256>>>(features,
                           lin1_w, lin1_b, bn1,
                           lin2_w, lin2_b, bn2,
                           lin3_w, lin3_b, bn3,
                           lin4_w, lin4_b, d_out);
}